// round 1
// baseline (speedup 1.0000x reference)
#include <cuda_runtime.h>
#include <math_constants.h>

// ---------------------------------------------------------------------------
// SelfAttention: out = softmax(Q K^T / sqrt(dk)) V with Q,K,V = x@W.T + b
// B=2, N=2048, D=1024, H=16, dk=64
// ---------------------------------------------------------------------------

#define B_SZ   2
#define SEQ    2048
#define DMODEL 1024
#define NHEAD  16
#define DK     64
#define MROWS  (B_SZ * SEQ)          // 4096

// Scratch for Q, K, V projections (16 MB each) — static device arrays (no alloc)
__device__ float g_Q[MROWS * DMODEL];
__device__ float g_K[MROWS * DMODEL];
__device__ float g_V[MROWS * DMODEL];

// ---------------------------------------------------------------------------
// Kernel A: tiled SGEMM  Y[m][n] = sum_k x[m][k] * W[n][k] + b[n]
// blockIdx.z in {0,1,2} selects (Wq->Q, Wk->K, Wv->V)
// Tile 64x64x16, 256 threads, 4x4 register blocking.
// ---------------------------------------------------------------------------
#define BM 64
#define BN 64
#define BK 16

__global__ __launch_bounds__(256)
void qkv_gemm_kernel(const float* __restrict__ x,
                     const float* __restrict__ Wq, const float* __restrict__ bq,
                     const float* __restrict__ Wk, const float* __restrict__ bk,
                     const float* __restrict__ Wv, const float* __restrict__ bv)
{
    const float* W;
    const float* bias;
    float* Y;
    if (blockIdx.z == 0)      { W = Wq; bias = bq; Y = g_Q; }
    else if (blockIdx.z == 1) { W = Wk; bias = bk; Y = g_K; }
    else                      { W = Wv; bias = bv; Y = g_V; }

    __shared__ float As[BK][BM + 1];
    __shared__ float Bs[BK][BN + 1];

    const int m0 = blockIdx.y * BM;
    const int n0 = blockIdx.x * BN;
    const int tx = threadIdx.x;   // 0..15 -> n
    const int ty = threadIdx.y;   // 0..15 -> m
    const int tid = ty * 16 + tx;

    float acc[4][4] = {};

    for (int k0 = 0; k0 < DMODEL; k0 += BK) {
        // load A tile (64 x 16) and B tile (64 x 16), K-major in smem
        #pragma unroll
        for (int i = tid; i < BM * BK; i += 256) {
            int m = i / BK, k = i % BK;
            As[k][m] = x[(m0 + m) * DMODEL + k0 + k];
        }
        #pragma unroll
        for (int i = tid; i < BN * BK; i += 256) {
            int n = i / BK, k = i % BK;
            Bs[k][n] = W[(n0 + n) * DMODEL + k0 + k];
        }
        __syncthreads();

        #pragma unroll
        for (int k = 0; k < BK; k++) {
            float a[4], b[4];
            #pragma unroll
            for (int ii = 0; ii < 4; ii++) a[ii] = As[k][ty * 4 + ii];
            #pragma unroll
            for (int jj = 0; jj < 4; jj++) b[jj] = Bs[k][tx * 4 + jj];
            #pragma unroll
            for (int ii = 0; ii < 4; ii++)
                #pragma unroll
                for (int jj = 0; jj < 4; jj++)
                    acc[ii][jj] += a[ii] * b[jj];
        }
        __syncthreads();
    }

    #pragma unroll
    for (int ii = 0; ii < 4; ii++) {
        int m = m0 + ty * 4 + ii;
        #pragma unroll
        for (int jj = 0; jj < 4; jj++) {
            int n = n0 + tx * 4 + jj;
            Y[m * DMODEL + n] = acc[ii][jj] + bias[n];
        }
    }
}

// ---------------------------------------------------------------------------
// Kernel B: flash attention. One block per (bh, 64-query tile).
// 256 threads (16x16). Thread (ty,tx): queries ty*4..+3, cols tx*4..+3.
// Shared: Qs (64x64), KVs (64x64, K then V reuse), Ps (64x64). stride 65.
// ---------------------------------------------------------------------------
#define SQ  64
#define SKV 64
#define LDS 65   // padded stride to avoid smem bank conflicts

__global__ __launch_bounds__(256)
void flash_attn_kernel(float* __restrict__ out)
{
    extern __shared__ float sm[];
    float* Qs  = sm;                    // SQ  * LDS
    float* KVs = sm + SQ * LDS;         // SKV * LDS
    float* Ps  = sm + 2 * SQ * LDS;     // SQ  * LDS

    const int qt = blockIdx.x;              // query tile 0..31
    const int bh = blockIdx.y;              // 0..31
    const int b  = bh / NHEAD;
    const int h  = bh % NHEAD;

    const int tx = threadIdx.x;
    const int ty = threadIdx.y;
    const int tid = ty * 16 + tx;

    const int q0 = qt * SQ;
    const size_t base = (size_t)b * SEQ * DMODEL + (size_t)h * DK;
    const float scale = 0.125f;  // 1/sqrt(64)

    // load Q tile: 64 queries x 64 dims
    #pragma unroll
    for (int i = tid; i < SQ * DK; i += 256) {
        int q = i / DK, d = i % DK;
        Qs[q * LDS + d] = g_Q[base + (size_t)(q0 + q) * DMODEL + d];
    }
    __syncthreads();

    float m_i[4], l_i[4], o[4][4];
    #pragma unroll
    for (int ii = 0; ii < 4; ii++) {
        m_i[ii] = -CUDART_INF_F;
        l_i[ii] = 0.f;
        #pragma unroll
        for (int jj = 0; jj < 4; jj++) o[ii][jj] = 0.f;
    }

    for (int kt = 0; kt < SEQ / SKV; kt++) {
        // ---- load K tile ----
        #pragma unroll
        for (int i = tid; i < SKV * DK; i += 256) {
            int j = i / DK, d = i % DK;
            KVs[j * LDS + d] = g_K[base + (size_t)(kt * SKV + j) * DMODEL + d];
        }
        __syncthreads();

        // ---- S = scale * Q K^T ----
        float s[4][4] = {};
        #pragma unroll 8
        for (int d = 0; d < DK; d++) {
            float a[4], bb[4];
            #pragma unroll
            for (int ii = 0; ii < 4; ii++) a[ii]  = Qs[(ty * 4 + ii) * LDS + d];
            #pragma unroll
            for (int jj = 0; jj < 4; jj++) bb[jj] = KVs[(tx * 4 + jj) * LDS + d];
            #pragma unroll
            for (int ii = 0; ii < 4; ii++)
                #pragma unroll
                for (int jj = 0; jj < 4; jj++)
                    s[ii][jj] += a[ii] * bb[jj];
        }

        // ---- online softmax (per query row; rows are owned by the 16 tx
        //      lanes sharing the same ty -> shuffle-reduce over 16 lanes) ----
        #pragma unroll
        for (int ii = 0; ii < 4; ii++) {
            float tmax = -CUDART_INF_F;
            #pragma unroll
            for (int jj = 0; jj < 4; jj++) {
                s[ii][jj] *= scale;
                tmax = fmaxf(tmax, s[ii][jj]);
            }
            #pragma unroll
            for (int off = 8; off >= 1; off >>= 1)
                tmax = fmaxf(tmax, __shfl_xor_sync(0xffffffffu, tmax, off));

            float m_new = fmaxf(m_i[ii], tmax);
            float alpha = __expf(m_i[ii] - m_new);   // 0 when m_i = -inf

            float rsum = 0.f;
            float p[4];
            #pragma unroll
            for (int jj = 0; jj < 4; jj++) {
                p[jj] = __expf(s[ii][jj] - m_new);
                rsum += p[jj];
            }
            #pragma unroll
            for (int off = 8; off >= 1; off >>= 1)
                rsum += __shfl_xor_sync(0xffffffffu, rsum, off);

            l_i[ii] = l_i[ii] * alpha + rsum;
            m_i[ii] = m_new;
            #pragma unroll
            for (int jj = 0; jj < 4; jj++) {
                o[ii][jj] *= alpha;
                Ps[(ty * 4 + ii) * LDS + tx * 4 + jj] = p[jj];
            }
        }
        __syncthreads();   // Ps written; everyone done reading K tile

        // ---- load V tile into the same buffer ----
        #pragma unroll
        for (int i = tid; i < SKV * DK; i += 256) {
            int j = i / DK, d = i % DK;
            KVs[j * LDS + d] = g_V[base + (size_t)(kt * SKV + j) * DMODEL + d];
        }
        __syncthreads();

        // ---- O += P V ----
        #pragma unroll 8
        for (int j = 0; j < SKV; j++) {
            float pa[4], vb[4];
            #pragma unroll
            for (int ii = 0; ii < 4; ii++) pa[ii] = Ps[(ty * 4 + ii) * LDS + j];
            #pragma unroll
            for (int jj = 0; jj < 4; jj++) vb[jj] = KVs[j * LDS + tx * 4 + jj];
            #pragma unroll
            for (int ii = 0; ii < 4; ii++)
                #pragma unroll
                for (int jj = 0; jj < 4; jj++)
                    o[ii][jj] += pa[ii] * vb[jj];
        }
        __syncthreads();   // done reading V before next K load
    }

    // ---- normalize and write out: out[b, q, h*64 + d] ----
    #pragma unroll
    for (int ii = 0; ii < 4; ii++) {
        float inv_l = 1.f / l_i[ii];
        int q = q0 + ty * 4 + ii;
        #pragma unroll
        for (int jj = 0; jj < 4; jj++) {
            int d = tx * 4 + jj;
            out[base + (size_t)q * DMODEL + d] = o[ii][jj] * inv_l;
        }
    }
}

// ---------------------------------------------------------------------------

extern "C" void kernel_launch(void* const* d_in, const int* in_sizes, int n_in,
                              void* d_out, int out_size)
{
    const float* x  = (const float*)d_in[0];
    const float* Wq = (const float*)d_in[1];
    const float* bq = (const float*)d_in[2];
    const float* Wk = (const float*)d_in[3];
    const float* bk = (const float*)d_in[4];
    const float* Wv = (const float*)d_in[5];
    const float* bv = (const float*)d_in[6];
    float* out = (float*)d_out;

    // QKV projections
    {
        dim3 grid(DMODEL / BN, MROWS / BM, 3);
        dim3 block(16, 16);
        qkv_gemm_kernel<<<grid, block>>>(x, Wq, bq, Wk, bk, Wv, bv);
    }

    // Flash attention
    {
        int smem = 3 * SQ * LDS * (int)sizeof(float);  // 49920 B
        static bool attr_set = false;
        // setting the attribute is idempotent and not a stream op; safe under capture
        cudaFuncSetAttribute(flash_attn_kernel,
                             cudaFuncAttributeMaxDynamicSharedMemorySize, smem);
        (void)attr_set;
        dim3 grid(SEQ / SQ, B_SZ * NHEAD);
        dim3 block(16, 16);
        flash_attn_kernel<<<grid, block, smem>>>(out);
    }
}

// round 2
// speedup vs baseline: 1.0016x; 1.0016x over previous
#include <cuda_runtime.h>
#include <math_constants.h>

// ---------------------------------------------------------------------------
// SelfAttention: out = softmax(Q K^T / sqrt(dk)) V with Q,K,V = x@W.T + b
// B=2, N=2048, D=1024, H=16, dk=64
// ---------------------------------------------------------------------------

#define B_SZ   2
#define SEQ    2048
#define DMODEL 1024
#define NHEAD  16
#define DK     64
#define MROWS  (B_SZ * SEQ)          // 4096

// Scratch for Q, K, V projections (16 MB each) — static device arrays (no alloc)
__device__ float g_Q[MROWS * DMODEL];
__device__ float g_K[MROWS * DMODEL];
__device__ float g_V[MROWS * DMODEL];

// ---------------------------------------------------------------------------
// Kernel A: tiled SGEMM  Y[m][n] = sum_k x[m][k] * W[n][k] + b[n]
// blockIdx.z in {0,1,2} selects (Wq->Q, Wk->K, Wv->V)
// Tile 64x64x16, 256 threads, 4x4 register blocking.
// ---------------------------------------------------------------------------
#define BM 64
#define BN 64
#define BK 16

__global__ __launch_bounds__(256)
void qkv_gemm_kernel(const float* __restrict__ x,
                     const float* __restrict__ Wq, const float* __restrict__ bq,
                     const float* __restrict__ Wk, const float* __restrict__ bk,
                     const float* __restrict__ Wv, const float* __restrict__ bv)
{
    const float* W;
    const float* bias;
    float* Y;
    if (blockIdx.z == 0)      { W = Wq; bias = bq; Y = g_Q; }
    else if (blockIdx.z == 1) { W = Wk; bias = bk; Y = g_K; }
    else                      { W = Wv; bias = bv; Y = g_V; }

    __shared__ float As[BK][BM + 1];
    __shared__ float Bs[BK][BN + 1];

    const int m0 = blockIdx.y * BM;
    const int n0 = blockIdx.x * BN;
    const int tx = threadIdx.x;   // 0..15 -> n
    const int ty = threadIdx.y;   // 0..15 -> m
    const int tid = ty * 16 + tx;

    float acc[4][4] = {};

    for (int k0 = 0; k0 < DMODEL; k0 += BK) {
        // load A tile (64 x 16) and B tile (64 x 16), K-major in smem
        #pragma unroll
        for (int i = tid; i < BM * BK; i += 256) {
            int m = i / BK, k = i % BK;
            As[k][m] = x[(m0 + m) * DMODEL + k0 + k];
        }
        #pragma unroll
        for (int i = tid; i < BN * BK; i += 256) {
            int n = i / BK, k = i % BK;
            Bs[k][n] = W[(n0 + n) * DMODEL + k0 + k];
        }
        __syncthreads();

        #pragma unroll
        for (int k = 0; k < BK; k++) {
            float a[4], b[4];
            #pragma unroll
            for (int ii = 0; ii < 4; ii++) a[ii] = As[k][ty * 4 + ii];
            #pragma unroll
            for (int jj = 0; jj < 4; jj++) b[jj] = Bs[k][tx * 4 + jj];
            #pragma unroll
            for (int ii = 0; ii < 4; ii++)
                #pragma unroll
                for (int jj = 0; jj < 4; jj++)
                    acc[ii][jj] += a[ii] * b[jj];
        }
        __syncthreads();
    }

    #pragma unroll
    for (int ii = 0; ii < 4; ii++) {
        int m = m0 + ty * 4 + ii;
        #pragma unroll
        for (int jj = 0; jj < 4; jj++) {
            int n = n0 + tx * 4 + jj;
            Y[m * DMODEL + n] = acc[ii][jj] + bias[n];
        }
    }
}

// ---------------------------------------------------------------------------
// Kernel B: flash attention. One block per (bh, 64-query tile).
// 256 threads (16x16). Thread (ty,tx): queries ty*4..+3, cols tx*4..+3.
// Shared: Qs (64x64), KVs (64x64, K then V reuse), Ps (64x64). stride 65.
// ---------------------------------------------------------------------------
#define SQ  64
#define SKV 64
#define LDS 65   // padded stride to avoid smem bank conflicts

__global__ __launch_bounds__(256)
void flash_attn_kernel(float* __restrict__ out)
{
    extern __shared__ float sm[];
    float* Qs  = sm;                    // SQ  * LDS
    float* KVs = sm + SQ * LDS;         // SKV * LDS
    float* Ps  = sm + 2 * SQ * LDS;     // SQ  * LDS

    const int qt = blockIdx.x;              // query tile 0..31
    const int bh = blockIdx.y;              // 0..31
    const int b  = bh / NHEAD;
    const int h  = bh % NHEAD;

    const int tx = threadIdx.x;
    const int ty = threadIdx.y;
    const int tid = ty * 16 + tx;

    const int q0 = qt * SQ;
    const size_t base = (size_t)b * SEQ * DMODEL + (size_t)h * DK;
    const float scale = 0.125f;  // 1/sqrt(64)

    // load Q tile: 64 queries x 64 dims
    #pragma unroll
    for (int i = tid; i < SQ * DK; i += 256) {
        int q = i / DK, d = i % DK;
        Qs[q * LDS + d] = g_Q[base + (size_t)(q0 + q) * DMODEL + d];
    }
    __syncthreads();

    float m_i[4], l_i[4], o[4][4];
    #pragma unroll
    for (int ii = 0; ii < 4; ii++) {
        m_i[ii] = -CUDART_INF_F;
        l_i[ii] = 0.f;
        #pragma unroll
        for (int jj = 0; jj < 4; jj++) o[ii][jj] = 0.f;
    }

    for (int kt = 0; kt < SEQ / SKV; kt++) {
        // ---- load K tile ----
        #pragma unroll
        for (int i = tid; i < SKV * DK; i += 256) {
            int j = i / DK, d = i % DK;
            KVs[j * LDS + d] = g_K[base + (size_t)(kt * SKV + j) * DMODEL + d];
        }
        __syncthreads();

        // ---- S = scale * Q K^T ----
        float s[4][4] = {};
        #pragma unroll 8
        for (int d = 0; d < DK; d++) {
            float a[4], bb[4];
            #pragma unroll
            for (int ii = 0; ii < 4; ii++) a[ii]  = Qs[(ty * 4 + ii) * LDS + d];
            #pragma unroll
            for (int jj = 0; jj < 4; jj++) bb[jj] = KVs[(tx * 4 + jj) * LDS + d];
            #pragma unroll
            for (int ii = 0; ii < 4; ii++)
                #pragma unroll
                for (int jj = 0; jj < 4; jj++)
                    s[ii][jj] += a[ii] * bb[jj];
        }

        // ---- online softmax (per query row; rows are owned by the 16 tx
        //      lanes sharing the same ty -> shuffle-reduce over 16 lanes) ----
        #pragma unroll
        for (int ii = 0; ii < 4; ii++) {
            float tmax = -CUDART_INF_F;
            #pragma unroll
            for (int jj = 0; jj < 4; jj++) {
                s[ii][jj] *= scale;
                tmax = fmaxf(tmax, s[ii][jj]);
            }
            #pragma unroll
            for (int off = 8; off >= 1; off >>= 1)
                tmax = fmaxf(tmax, __shfl_xor_sync(0xffffffffu, tmax, off));

            float m_new = fmaxf(m_i[ii], tmax);
            float alpha = __expf(m_i[ii] - m_new);   // 0 when m_i = -inf

            float rsum = 0.f;
            float p[4];
            #pragma unroll
            for (int jj = 0; jj < 4; jj++) {
                p[jj] = __expf(s[ii][jj] - m_new);
                rsum += p[jj];
            }
            #pragma unroll
            for (int off = 8; off >= 1; off >>= 1)
                rsum += __shfl_xor_sync(0xffffffffu, rsum, off);

            l_i[ii] = l_i[ii] * alpha + rsum;
            m_i[ii] = m_new;
            #pragma unroll
            for (int jj = 0; jj < 4; jj++) {
                o[ii][jj] *= alpha;
                Ps[(ty * 4 + ii) * LDS + tx * 4 + jj] = p[jj];
            }
        }
        __syncthreads();   // Ps written; everyone done reading K tile

        // ---- load V tile into the same buffer ----
        #pragma unroll
        for (int i = tid; i < SKV * DK; i += 256) {
            int j = i / DK, d = i % DK;
            KVs[j * LDS + d] = g_V[base + (size_t)(kt * SKV + j) * DMODEL + d];
        }
        __syncthreads();

        // ---- O += P V ----
        #pragma unroll 8
        for (int j = 0; j < SKV; j++) {
            float pa[4], vb[4];
            #pragma unroll
            for (int ii = 0; ii < 4; ii++) pa[ii] = Ps[(ty * 4 + ii) * LDS + j];
            #pragma unroll
            for (int jj = 0; jj < 4; jj++) vb[jj] = KVs[j * LDS + tx * 4 + jj];
            #pragma unroll
            for (int ii = 0; ii < 4; ii++)
                #pragma unroll
                for (int jj = 0; jj < 4; jj++)
                    o[ii][jj] += pa[ii] * vb[jj];
        }
        __syncthreads();   // done reading V before next K load
    }

    // ---- normalize and write out: out[b, q, h*64 + d] ----
    #pragma unroll
    for (int ii = 0; ii < 4; ii++) {
        float inv_l = 1.f / l_i[ii];
        int q = q0 + ty * 4 + ii;
        #pragma unroll
        for (int jj = 0; jj < 4; jj++) {
            int d = tx * 4 + jj;
            out[base + (size_t)q * DMODEL + d] = o[ii][jj] * inv_l;
        }
    }
}

// ---------------------------------------------------------------------------

extern "C" void kernel_launch(void* const* d_in, const int* in_sizes, int n_in,
                              void* d_out, int out_size)
{
    const float* x  = (const float*)d_in[0];
    const float* Wq = (const float*)d_in[1];
    const float* bq = (const float*)d_in[2];
    const float* Wk = (const float*)d_in[3];
    const float* bk = (const float*)d_in[4];
    const float* Wv = (const float*)d_in[5];
    const float* bv = (const float*)d_in[6];
    float* out = (float*)d_out;

    // QKV projections
    {
        dim3 grid(DMODEL / BN, MROWS / BM, 3);
        dim3 block(16, 16);
        qkv_gemm_kernel<<<grid, block>>>(x, Wq, bq, Wk, bk, Wv, bv);
    }

    // Flash attention
    {
        int smem = 3 * SQ * LDS * (int)sizeof(float);  // 49920 B
        static bool attr_set = false;
        // setting the attribute is idempotent and not a stream op; safe under capture
        cudaFuncSetAttribute(flash_attn_kernel,
                             cudaFuncAttributeMaxDynamicSharedMemorySize, smem);
        (void)attr_set;
        dim3 grid(SEQ / SQ, B_SZ * NHEAD);
        dim3 block(16, 16);
        flash_attn_kernel<<<grid, block, smem>>>(out);
    }
}

// round 3
// speedup vs baseline: 1.5561x; 1.5537x over previous
#include <cuda_runtime.h>
#include <math_constants.h>
#include <cstdint>

// ---------------------------------------------------------------------------
// SelfAttention via tf32 tensor-core mma (m16n8k8), split-tf32 for precision.
// B=2, N=2048, D=1024, H=16, dk=64
// ---------------------------------------------------------------------------

#define B_SZ   2
#define SEQ    2048
#define DMODEL 1024
#define NHEAD  16
#define DK     64
#define MROWS  (B_SZ * SEQ)          // 4096

__device__ float g_Q[MROWS * DMODEL];
__device__ float g_K[MROWS * DMODEL];
__device__ float g_V[MROWS * DMODEL];

__device__ __forceinline__ uint32_t f2tf(float f) {
    uint32_t u;
    asm("cvt.rna.tf32.f32 %0, %1;" : "=r"(u) : "f"(f));
    return u;
}
__device__ __forceinline__ void split_tf(float v, uint32_t& hi, uint32_t& lo) {
    hi = f2tf(v);
    lo = f2tf(v - __uint_as_float(hi));
}
__device__ __forceinline__ void mma8(float* d,
                                     uint32_t a0, uint32_t a1, uint32_t a2, uint32_t a3,
                                     uint32_t b0, uint32_t b1) {
    asm volatile(
        "mma.sync.aligned.m16n8k8.row.col.f32.tf32.tf32.f32 "
        "{%0,%1,%2,%3}, {%4,%5,%6,%7}, {%8,%9}, {%0,%1,%2,%3};"
        : "+f"(d[0]), "+f"(d[1]), "+f"(d[2]), "+f"(d[3])
        : "r"(a0), "r"(a1), "r"(a2), "r"(a3), "r"(b0), "r"(b1));
}

// ---------------------------------------------------------------------------
// Kernel A: Y[m][n] = sum_k x[m][k]*W[n][k] + b[n], split-tf32 (3 mma).
// Block tile 128x128, k-tile 32. 256 threads = 8 warps (4M x 2N),
// warp tile 32x64. Smem holds (hi,lo) uint2 pairs, [k][m] stride 130.
// ---------------------------------------------------------------------------
#define GST 130

__global__ __launch_bounds__(256, 1)
void qkv_mma_kernel(const float* __restrict__ x,
                    const float* __restrict__ Wq, const float* __restrict__ bq,
                    const float* __restrict__ Wk, const float* __restrict__ bk,
                    const float* __restrict__ Wv, const float* __restrict__ bv)
{
    extern __shared__ uint2 gsm[];
    uint2* As = gsm;               // 32*130 pairs
    uint2* Bs = gsm + 32 * GST;    // 32*130 pairs

    const float *W, *bias;
    float* Y;
    if (blockIdx.z == 0)      { W = Wq; bias = bq; Y = g_Q; }
    else if (blockIdx.z == 1) { W = Wk; bias = bk; Y = g_K; }
    else                      { W = Wv; bias = bv; Y = g_V; }

    const int tid  = threadIdx.x;
    const int lane = tid & 31;
    const int warp = tid >> 5;
    const int gid  = lane >> 2;
    const int tig  = lane & 3;
    const int wm   = warp & 3;
    const int wn   = warp >> 2;
    const int m0   = blockIdx.y * 128;
    const int n0   = blockIdx.x * 128;

    float acc[2][8][4];
    #pragma unroll
    for (int mf = 0; mf < 2; mf++)
        #pragma unroll
        for (int nf = 0; nf < 8; nf++)
            #pragma unroll
            for (int c = 0; c < 4; c++) acc[mf][nf][c] = 0.f;

    for (int k0 = 0; k0 < DMODEL; k0 += 32) {
        // ---- stage tiles, split into (hi,lo) tf32 pairs ----
        #pragma unroll
        for (int t = 0; t < 4; t++) {
            int i  = t * 256 + tid;
            int r  = i >> 3;
            int c4 = (i & 7) * 4;
            float4 va = *reinterpret_cast<const float4*>(&x[(size_t)(m0 + r) * DMODEL + k0 + c4]);
            float4 vb = *reinterpret_cast<const float4*>(&W[(size_t)(n0 + r) * DMODEL + k0 + c4]);
            uint32_t h, l;
            split_tf(va.x, h, l); As[(c4 + 0) * GST + r] = make_uint2(h, l);
            split_tf(va.y, h, l); As[(c4 + 1) * GST + r] = make_uint2(h, l);
            split_tf(va.z, h, l); As[(c4 + 2) * GST + r] = make_uint2(h, l);
            split_tf(va.w, h, l); As[(c4 + 3) * GST + r] = make_uint2(h, l);
            split_tf(vb.x, h, l); Bs[(c4 + 0) * GST + r] = make_uint2(h, l);
            split_tf(vb.y, h, l); Bs[(c4 + 1) * GST + r] = make_uint2(h, l);
            split_tf(vb.z, h, l); Bs[(c4 + 2) * GST + r] = make_uint2(h, l);
            split_tf(vb.w, h, l); Bs[(c4 + 3) * GST + r] = make_uint2(h, l);
        }
        __syncthreads();

        #pragma unroll
        for (int ks = 0; ks < 4; ks++) {
            const int kb = ks * 8;
            uint2 A0[2], A1[2], A2[2], A3[2];
            #pragma unroll
            for (int mf = 0; mf < 2; mf++) {
                int m = wm * 32 + mf * 16;
                A0[mf] = As[(kb + tig) * GST + m + gid];
                A1[mf] = As[(kb + tig) * GST + m + gid + 8];
                A2[mf] = As[(kb + tig + 4) * GST + m + gid];
                A3[mf] = As[(kb + tig + 4) * GST + m + gid + 8];
            }
            #pragma unroll
            for (int nf = 0; nf < 8; nf++) {
                int n = wn * 64 + nf * 8 + gid;
                uint2 B0 = Bs[(kb + tig) * GST + n];
                uint2 B1 = Bs[(kb + tig + 4) * GST + n];
                #pragma unroll
                for (int mf = 0; mf < 2; mf++) {
                    mma8(acc[mf][nf], A0[mf].x, A1[mf].x, A2[mf].x, A3[mf].x, B0.x, B1.x);
                    mma8(acc[mf][nf], A0[mf].x, A1[mf].x, A2[mf].x, A3[mf].x, B0.y, B1.y);
                    mma8(acc[mf][nf], A0[mf].y, A1[mf].y, A2[mf].y, A3[mf].y, B0.x, B1.x);
                }
            }
        }
        __syncthreads();
    }

    // ---- epilogue: add bias, write fp32 ----
    #pragma unroll
    for (int mf = 0; mf < 2; mf++) {
        int row = m0 + wm * 32 + mf * 16 + gid;
        #pragma unroll
        for (int nf = 0; nf < 8; nf++) {
            int col = n0 + wn * 64 + nf * 8 + 2 * tig;
            float b0 = bias[col], b1 = bias[col + 1];
            *reinterpret_cast<float2*>(&Y[(size_t)row * DMODEL + col]) =
                make_float2(acc[mf][nf][0] + b0, acc[mf][nf][1] + b1);
            *reinterpret_cast<float2*>(&Y[(size_t)(row + 8) * DMODEL + col]) =
                make_float2(acc[mf][nf][2] + b0, acc[mf][nf][3] + b1);
        }
    }
}

// ---------------------------------------------------------------------------
// Kernel B: flash attention with tf32 mma.
// Block = (64-query tile, bh). 128 threads = 4 warps; warp owns 16 q rows.
// S = QK^T plain tf32 (Q scaled at stage time); PV with P split (2 mma).
// ---------------------------------------------------------------------------
#define QST 65   // u32 stride for Qs/Ks/Vs rows
#define PST 66   // uint2 stride for P rows (even, so uint4 stores are aligned)

__global__ __launch_bounds__(128, 2)
void flash_mma_kernel(float* __restrict__ out)
{
    extern __shared__ uint32_t smem_u[];
    uint32_t* Qs = smem_u;             // 64 * 65
    uint32_t* Ks = Qs + 64 * QST;      // 64 * 65
    uint32_t* Vs = Ks + 64 * QST;      // 64 * 65
    uint2*    Ps = reinterpret_cast<uint2*>(Vs + 64 * QST);  // 4 * 16 * 66 pairs

    const int tid  = threadIdx.x;
    const int lane = tid & 31;
    const int w    = tid >> 5;
    const int gid  = lane >> 2;
    const int tig  = lane & 3;

    const int qt = blockIdx.x;
    const int bh = blockIdx.y;
    const int b  = bh >> 4;
    const int h  = bh & 15;
    const int q0 = qt * 64;
    const size_t base = (size_t)b * SEQ * DMODEL + (size_t)h * DK;

    // ---- stage Q tile (scale 1/8 folded in) ----
    #pragma unroll
    for (int t = 0; t < 8; t++) {
        int i = t * 128 + tid;
        int r = i >> 4;
        int c = (i & 15) * 4;
        float4 v = *reinterpret_cast<const float4*>(&g_Q[base + (size_t)(q0 + r) * DMODEL + c]);
        Qs[r * QST + c + 0] = f2tf(0.125f * v.x);
        Qs[r * QST + c + 1] = f2tf(0.125f * v.y);
        Qs[r * QST + c + 2] = f2tf(0.125f * v.z);
        Qs[r * QST + c + 3] = f2tf(0.125f * v.w);
    }
    __syncthreads();

    // ---- Q fragments to registers (A-layout), 8 k-frags ----
    uint32_t qa[8][4];
    {
        int r = w * 16 + gid;
        #pragma unroll
        for (int kf = 0; kf < 8; kf++) {
            qa[kf][0] = Qs[r * QST + kf * 8 + tig];
            qa[kf][1] = Qs[(r + 8) * QST + kf * 8 + tig];
            qa[kf][2] = Qs[r * QST + kf * 8 + tig + 4];
            qa[kf][3] = Qs[(r + 8) * QST + kf * 8 + tig + 4];
        }
    }

    float m_i[2] = {-CUDART_INF_F, -CUDART_INF_F};
    float l_i[2] = {0.f, 0.f};
    float o[8][4];
    #pragma unroll
    for (int nf = 0; nf < 8; nf++)
        #pragma unroll
        for (int c = 0; c < 4; c++) o[nf][c] = 0.f;

    uint2* Pw = Ps + w * 16 * PST;

    for (int kt = 0; kt < SEQ / 64; kt++) {
        // ---- stage K and V tiles (tf32) ----
        #pragma unroll
        for (int t = 0; t < 8; t++) {
            int i = t * 128 + tid;
            int r = i >> 4;
            int c = (i & 15) * 4;
            size_t g = base + (size_t)(kt * 64 + r) * DMODEL + c;
            float4 vk = *reinterpret_cast<const float4*>(&g_K[g]);
            float4 vv = *reinterpret_cast<const float4*>(&g_V[g]);
            Ks[r * QST + c + 0] = f2tf(vk.x);
            Ks[r * QST + c + 1] = f2tf(vk.y);
            Ks[r * QST + c + 2] = f2tf(vk.z);
            Ks[r * QST + c + 3] = f2tf(vk.w);
            Vs[r * QST + c + 0] = f2tf(vv.x);
            Vs[r * QST + c + 1] = f2tf(vv.y);
            Vs[r * QST + c + 2] = f2tf(vv.z);
            Vs[r * QST + c + 3] = f2tf(vv.w);
        }
        __syncthreads();

        // ---- S = Q K^T (already scaled) ----
        float s[8][4];
        #pragma unroll
        for (int nf = 0; nf < 8; nf++)
            #pragma unroll
            for (int c = 0; c < 4; c++) s[nf][c] = 0.f;

        #pragma unroll
        for (int kf = 0; kf < 8; kf++) {
            #pragma unroll
            for (int nf = 0; nf < 8; nf++) {
                uint32_t b0 = Ks[(nf * 8 + gid) * QST + kf * 8 + tig];
                uint32_t b1 = Ks[(nf * 8 + gid) * QST + kf * 8 + tig + 4];
                mma8(s[nf], qa[kf][0], qa[kf][1], qa[kf][2], qa[kf][3], b0, b1);
            }
        }

        // ---- online softmax on C-fragments; write split-P to smem ----
        #pragma unroll
        for (int hf = 0; hf < 2; hf++) {
            float mx = -CUDART_INF_F;
            #pragma unroll
            for (int nf = 0; nf < 8; nf++)
                mx = fmaxf(mx, fmaxf(s[nf][2 * hf], s[nf][2 * hf + 1]));
            mx = fmaxf(mx, __shfl_xor_sync(0xffffffffu, mx, 1));
            mx = fmaxf(mx, __shfl_xor_sync(0xffffffffu, mx, 2));

            float m_new = fmaxf(m_i[hf], mx);
            float alpha = __expf(m_i[hf] - m_new);
            float sum = 0.f;
            int row = gid + 8 * hf;
            #pragma unroll
            for (int nf = 0; nf < 8; nf++) {
                float p0 = __expf(s[nf][2 * hf] - m_new);
                float p1 = __expf(s[nf][2 * hf + 1] - m_new);
                sum += p0 + p1;
                uint32_t h0, l0, h1, l1;
                split_tf(p0, h0, l0);
                split_tf(p1, h1, l1);
                *reinterpret_cast<uint4*>(&Pw[row * PST + nf * 8 + 2 * tig]) =
                    make_uint4(h0, l0, h1, l1);
                o[nf][2 * hf]     *= alpha;
                o[nf][2 * hf + 1] *= alpha;
            }
            sum += __shfl_xor_sync(0xffffffffu, sum, 1);
            sum += __shfl_xor_sync(0xffffffffu, sum, 2);
            l_i[hf] = l_i[hf] * alpha + sum;
            m_i[hf] = m_new;
        }
        __syncwarp();

        // ---- O += P V  (P split: hi + lo) ----
        #pragma unroll
        for (int kf = 0; kf < 8; kf++) {
            uint2 a0 = Pw[gid * PST + kf * 8 + tig];
            uint2 a1 = Pw[(gid + 8) * PST + kf * 8 + tig];
            uint2 a2 = Pw[gid * PST + kf * 8 + tig + 4];
            uint2 a3 = Pw[(gid + 8) * PST + kf * 8 + tig + 4];
            #pragma unroll
            for (int nf = 0; nf < 8; nf++) {
                uint32_t b0 = Vs[(kf * 8 + tig) * QST + nf * 8 + gid];
                uint32_t b1 = Vs[(kf * 8 + tig + 4) * QST + nf * 8 + gid];
                mma8(o[nf], a0.x, a1.x, a2.x, a3.x, b0, b1);
                mma8(o[nf], a0.y, a1.y, a2.y, a3.y, b0, b1);
            }
        }
        __syncthreads();   // all warps done with Ks/Vs before next stage
    }

    // ---- normalize and store ----
    float inv0 = 1.f / l_i[0];
    float inv1 = 1.f / l_i[1];
    int row = q0 + w * 16 + gid;
    #pragma unroll
    for (int nf = 0; nf < 8; nf++) {
        int col = nf * 8 + 2 * tig;
        *reinterpret_cast<float2*>(&out[base + (size_t)row * DMODEL + col]) =
            make_float2(o[nf][0] * inv0, o[nf][1] * inv0);
        *reinterpret_cast<float2*>(&out[base + (size_t)(row + 8) * DMODEL + col]) =
            make_float2(o[nf][2] * inv1, o[nf][3] * inv1);
    }
}

// ---------------------------------------------------------------------------

extern "C" void kernel_launch(void* const* d_in, const int* in_sizes, int n_in,
                              void* d_out, int out_size)
{
    const float* x  = (const float*)d_in[0];
    const float* Wq = (const float*)d_in[1];
    const float* bq = (const float*)d_in[2];
    const float* Wk = (const float*)d_in[3];
    const float* bk = (const float*)d_in[4];
    const float* Wv = (const float*)d_in[5];
    const float* bv = (const float*)d_in[6];
    float* out = (float*)d_out;

    // QKV projections (split-tf32 mma)
    {
        int smem = 2 * 32 * GST * (int)sizeof(uint2);   // 66560 B
        cudaFuncSetAttribute(qkv_mma_kernel,
                             cudaFuncAttributeMaxDynamicSharedMemorySize, smem);
        dim3 grid(DMODEL / 128, MROWS / 128, 3);
        qkv_mma_kernel<<<grid, 256, smem>>>(x, Wq, bq, Wk, bk, Wv, bv);
    }

    // Flash attention (tf32 mma)
    {
        int smem = 3 * 64 * QST * (int)sizeof(uint32_t)      // Qs,Ks,Vs
                 + 4 * 16 * PST * (int)sizeof(uint2);        // P buffers
        cudaFuncSetAttribute(flash_mma_kernel,
                             cudaFuncAttributeMaxDynamicSharedMemorySize, smem);
        dim3 grid(SEQ / 64, B_SZ * NHEAD);
        flash_mma_kernel<<<grid, 128, smem>>>(out);
    }
}

// round 4
// speedup vs baseline: 3.8372x; 2.4659x over previous
#include <cuda_runtime.h>
#include <cuda_bf16.h>
#include <math_constants.h>
#include <cstdint>

// ---------------------------------------------------------------------------
// SelfAttention: tf32 S-path + split-bf16 everywhere else.
// B=2, N=2048, D=1024, H=16, dk=64
// ---------------------------------------------------------------------------

#define B_SZ   2
#define SEQ    2048
#define DMODEL 1024
#define NHEAD  16
#define DK     64
#define MROWS  (B_SZ * SEQ)          // 4096

// GEMM outputs, pre-formatted for the attention kernel:
//  Q: tf32-rounded fp32 bits, scale 1/8 folded in
//  K: tf32-rounded fp32 bits
//  V: split bf16 (hi, lo)
__device__ uint32_t       g_Qt[MROWS * DMODEL];
__device__ uint32_t       g_Kt[MROWS * DMODEL];
__device__ __nv_bfloat16  g_Vh[MROWS * DMODEL];
__device__ __nv_bfloat16  g_Vl[MROWS * DMODEL];

// ---------------------------------------------------------------------------
// helpers
// ---------------------------------------------------------------------------
__device__ __forceinline__ uint32_t f2tf(float f) {
    uint32_t u;
    asm("cvt.rna.tf32.f32 %0, %1;" : "=r"(u) : "f"(f));
    return u;
}

__device__ __forceinline__ void bsplit(float v, __nv_bfloat16& h, __nv_bfloat16& l) {
    h = __float2bfloat16(v);
    l = __float2bfloat16(v - __bfloat162float(h));
}

// pack two bf16 (lo = first element / lower k) into u32
__device__ __forceinline__ uint32_t pk(__nv_bfloat16 lo, __nv_bfloat16 hi) {
    __nv_bfloat162 t;
    t.x = lo; t.y = hi;
    return *reinterpret_cast<uint32_t*>(&t);
}

__device__ __forceinline__ uint32_t smem_u32(const void* p) {
    return (uint32_t)__cvta_generic_to_shared(p);
}

__device__ __forceinline__ void ldsm_x4(uint32_t& r0, uint32_t& r1, uint32_t& r2, uint32_t& r3,
                                        uint32_t addr) {
    asm volatile("ldmatrix.sync.aligned.m8n8.x4.shared.b16 {%0,%1,%2,%3}, [%4];"
                 : "=r"(r0), "=r"(r1), "=r"(r2), "=r"(r3) : "r"(addr));
}
__device__ __forceinline__ void ldsm_x4t(uint32_t& r0, uint32_t& r1, uint32_t& r2, uint32_t& r3,
                                         uint32_t addr) {
    asm volatile("ldmatrix.sync.aligned.m8n8.x4.trans.shared.b16 {%0,%1,%2,%3}, [%4];"
                 : "=r"(r0), "=r"(r1), "=r"(r2), "=r"(r3) : "r"(addr));
}

// tf32 m16n8k8
__device__ __forceinline__ void mma8(float* d,
                                     uint32_t a0, uint32_t a1, uint32_t a2, uint32_t a3,
                                     uint32_t b0, uint32_t b1) {
    asm volatile(
        "mma.sync.aligned.m16n8k8.row.col.f32.tf32.tf32.f32 "
        "{%0,%1,%2,%3}, {%4,%5,%6,%7}, {%8,%9}, {%0,%1,%2,%3};"
        : "+f"(d[0]), "+f"(d[1]), "+f"(d[2]), "+f"(d[3])
        : "r"(a0), "r"(a1), "r"(a2), "r"(a3), "r"(b0), "r"(b1));
}
// bf16 m16n8k16
__device__ __forceinline__ void mma16(float* d, const uint32_t* a,
                                      uint32_t b0, uint32_t b1) {
    asm volatile(
        "mma.sync.aligned.m16n8k16.row.col.f32.bf16.bf16.f32 "
        "{%0,%1,%2,%3}, {%4,%5,%6,%7}, {%8,%9}, {%0,%1,%2,%3};"
        : "+f"(d[0]), "+f"(d[1]), "+f"(d[2]), "+f"(d[3])
        : "r"(a[0]), "r"(a[1]), "r"(a[2]), "r"(a[3]), "r"(b0), "r"(b1));
}

// ---------------------------------------------------------------------------
// Kernel A: QKV projection, split-bf16 (3-term) m16n8k16.
// Block tile 128x128, BK=32. 256 threads = 8 warps (4M x 2N), warp tile 32x64.
// ---------------------------------------------------------------------------
#define AST 40   // bf16 stride (32 + 8 pad)

__global__ __launch_bounds__(256, 1)
void qkv_mma_kernel(const float* __restrict__ x,
                    const float* __restrict__ Wq, const float* __restrict__ bq,
                    const float* __restrict__ Wk, const float* __restrict__ bk,
                    const float* __restrict__ Wv, const float* __restrict__ bv)
{
    extern __shared__ __nv_bfloat16 gsm[];
    __nv_bfloat16* Ah = gsm;                 // 128*40
    __nv_bfloat16* Al = Ah + 128 * AST;
    __nv_bfloat16* Bh = Al + 128 * AST;
    __nv_bfloat16* Bl = Bh + 128 * AST;

    const float *W, *bias;
    const int z = blockIdx.z;
    if (z == 0)      { W = Wq; bias = bq; }
    else if (z == 1) { W = Wk; bias = bk; }
    else             { W = Wv; bias = bv; }

    const int tid  = threadIdx.x;
    const int lane = tid & 31;
    const int warp = tid >> 5;
    const int gid  = lane >> 2;
    const int tig  = lane & 3;
    const int wm   = warp & 3;
    const int wn   = warp >> 2;
    const int m0   = blockIdx.y * 128;
    const int n0   = blockIdx.x * 128;

    // ldmatrix per-lane offsets (bf16 units)
    const int a_off = (wm * 32 + (lane & 7) + ((lane >> 3) & 1) * 8) * AST + (lane >> 4) * 8;
    const int b_off = (wn * 64 + (lane & 7) + (lane >> 4) * 8) * AST + ((lane >> 3) & 1) * 8;

    const uint32_t sAh = smem_u32(Ah), sAl = smem_u32(Al);
    const uint32_t sBh = smem_u32(Bh), sBl = smem_u32(Bl);

    float acc[2][8][4];
    #pragma unroll
    for (int mf = 0; mf < 2; mf++)
        #pragma unroll
        for (int nf = 0; nf < 8; nf++)
            #pragma unroll
            for (int c = 0; c < 4; c++) acc[mf][nf][c] = 0.f;

    for (int k0 = 0; k0 < DMODEL; k0 += 32) {
        // ---- stage A and B tiles, split to (hi, lo) bf16 ----
        #pragma unroll
        for (int t = 0; t < 4; t++) {
            int i  = t * 256 + tid;
            int r  = i >> 3;
            int c4 = (i & 7) * 4;
            float4 va = *reinterpret_cast<const float4*>(&x[(size_t)(m0 + r) * DMODEL + k0 + c4]);
            __nv_bfloat16 h0, h1, h2, h3, l0, l1, l2, l3;
            bsplit(va.x, h0, l0); bsplit(va.y, h1, l1);
            bsplit(va.z, h2, l2); bsplit(va.w, h3, l3);
            *reinterpret_cast<uint2*>(&Ah[r * AST + c4]) = make_uint2(pk(h0, h1), pk(h2, h3));
            *reinterpret_cast<uint2*>(&Al[r * AST + c4]) = make_uint2(pk(l0, l1), pk(l2, l3));
        }
        #pragma unroll
        for (int t = 0; t < 4; t++) {
            int i  = t * 256 + tid;
            int r  = i >> 3;
            int c4 = (i & 7) * 4;
            float4 vb = *reinterpret_cast<const float4*>(&W[(size_t)(n0 + r) * DMODEL + k0 + c4]);
            __nv_bfloat16 h0, h1, h2, h3, l0, l1, l2, l3;
            bsplit(vb.x, h0, l0); bsplit(vb.y, h1, l1);
            bsplit(vb.z, h2, l2); bsplit(vb.w, h3, l3);
            *reinterpret_cast<uint2*>(&Bh[r * AST + c4]) = make_uint2(pk(h0, h1), pk(h2, h3));
            *reinterpret_cast<uint2*>(&Bl[r * AST + c4]) = make_uint2(pk(l0, l1), pk(l2, l3));
        }
        __syncthreads();

        // ---- A fragments ----
        uint32_t ah[2][2][4], al[2][2][4];   // [kc][mf][4]
        #pragma unroll
        for (int kc = 0; kc < 2; kc++)
            #pragma unroll
            for (int mf = 0; mf < 2; mf++) {
                int off = (a_off + mf * 16 * AST + kc * 16) * 2;
                ldsm_x4(ah[kc][mf][0], ah[kc][mf][1], ah[kc][mf][2], ah[kc][mf][3], sAh + off);
                ldsm_x4(al[kc][mf][0], al[kc][mf][1], al[kc][mf][2], al[kc][mf][3], sAl + off);
            }

        // ---- B fragments + mma ----
        #pragma unroll
        for (int kc = 0; kc < 2; kc++) {
            #pragma unroll
            for (int nfp = 0; nfp < 4; nfp++) {
                int off = (b_off + nfp * 16 * AST + kc * 16) * 2;
                uint32_t bh0, bh1, bh2, bh3, bl0, bl1, bl2, bl3;
                ldsm_x4(bh0, bh1, bh2, bh3, sBh + off);
                ldsm_x4(bl0, bl1, bl2, bl3, sBl + off);
                #pragma unroll
                for (int mf = 0; mf < 2; mf++) {
                    mma16(acc[mf][2 * nfp],     ah[kc][mf], bh0, bh1);
                    mma16(acc[mf][2 * nfp],     al[kc][mf], bh0, bh1);
                    mma16(acc[mf][2 * nfp],     ah[kc][mf], bl0, bl1);
                    mma16(acc[mf][2 * nfp + 1], ah[kc][mf], bh2, bh3);
                    mma16(acc[mf][2 * nfp + 1], al[kc][mf], bh2, bh3);
                    mma16(acc[mf][2 * nfp + 1], ah[kc][mf], bl2, bl3);
                }
            }
        }
        __syncthreads();
    }

    // ---- epilogue: + bias, format per consumer ----
    #pragma unroll
    for (int mf = 0; mf < 2; mf++) {
        int row = m0 + wm * 32 + mf * 16 + gid;
        #pragma unroll
        for (int nf = 0; nf < 8; nf++) {
            int col = n0 + wn * 64 + nf * 8 + 2 * tig;
            float b0 = bias[col], b1 = bias[col + 1];
            float v0 = acc[mf][nf][0] + b0;
            float v1 = acc[mf][nf][1] + b1;
            float v2 = acc[mf][nf][2] + b0;
            float v3 = acc[mf][nf][3] + b1;
            size_t i0 = (size_t)row * DMODEL + col;
            size_t i1 = (size_t)(row + 8) * DMODEL + col;
            if (z == 0) {
                *reinterpret_cast<uint2*>(&g_Qt[i0]) =
                    make_uint2(f2tf(0.125f * v0), f2tf(0.125f * v1));
                *reinterpret_cast<uint2*>(&g_Qt[i1]) =
                    make_uint2(f2tf(0.125f * v2), f2tf(0.125f * v3));
            } else if (z == 1) {
                *reinterpret_cast<uint2*>(&g_Kt[i0]) = make_uint2(f2tf(v0), f2tf(v1));
                *reinterpret_cast<uint2*>(&g_Kt[i1]) = make_uint2(f2tf(v2), f2tf(v3));
            } else {
                __nv_bfloat16 h0, h1, h2, h3, l0, l1, l2, l3;
                bsplit(v0, h0, l0); bsplit(v1, h1, l1);
                bsplit(v2, h2, l2); bsplit(v3, h3, l3);
                *reinterpret_cast<uint32_t*>(&g_Vh[i0]) = pk(h0, h1);
                *reinterpret_cast<uint32_t*>(&g_Vl[i0]) = pk(l0, l1);
                *reinterpret_cast<uint32_t*>(&g_Vh[i1]) = pk(h2, h3);
                *reinterpret_cast<uint32_t*>(&g_Vl[i1]) = pk(l2, l3);
            }
        }
    }
}

// ---------------------------------------------------------------------------
// Kernel B: flash attention.
//   S = Q K^T : tf32 m16n8k8, B-frags via u32-as-2xb16 ldmatrix trick.
//   P V       : split-bf16 m16n8k16, P register-resident, V via ldmatrix.trans.
// Block = (64-query tile, bh). 128 threads = 4 warps; warp owns 16 q rows.
// ---------------------------------------------------------------------------
#define KST 68   // u32 stride for Qs/Ks (64 + 4 pad)
#define VST 72   // bf16 stride for Vh/Vl (64 + 8 pad)

__global__ __launch_bounds__(128, 2)
void flash_mma_kernel(float* __restrict__ out)
{
    extern __shared__ uint32_t smem_u[];
    uint32_t*      Qs = smem_u;               // 64 * 68 u32
    uint32_t*      Ks = Qs + 64 * KST;        // 64 * 68 u32
    __nv_bfloat16* Vh = reinterpret_cast<__nv_bfloat16*>(Ks + 64 * KST); // 64*72
    __nv_bfloat16* Vl = Vh + 64 * VST;

    const int tid  = threadIdx.x;
    const int lane = tid & 31;
    const int w    = tid >> 5;
    const int gid  = lane >> 2;
    const int tig  = lane & 3;

    const int qt = blockIdx.x;
    const int bh = blockIdx.y;
    const int b  = bh >> 4;
    const int h  = bh & 15;
    const int q0 = qt * 64;
    const size_t base = (size_t)b * SEQ * DMODEL + (size_t)h * DK;

    // ldmatrix per-lane offsets
    // Q A-frag (u32 units): rows w*16 + ..., col within k-chunk
    const int q_off = (w * 16 + (lane & 7) + ((lane >> 3) & 1) * 8) * KST + (lane >> 4) * 4;
    // K B-frag (u32 units)
    const int k_off = ((lane & 7) + (lane >> 4) * 8) * KST + ((lane >> 3) & 1) * 4;
    // V B-frag (bf16 units)
    const int v_off = (lane & 15) * VST + (lane >> 4) * 8;

    const uint32_t sQ  = smem_u32(Qs);
    const uint32_t sK  = smem_u32(Ks);
    const uint32_t sVh = smem_u32(Vh);
    const uint32_t sVl = smem_u32(Vl);

    // ---- stage Q tile (already tf32 + scaled) ----
    #pragma unroll
    for (int t = 0; t < 8; t++) {
        int i = t * 128 + tid;
        int r = i >> 4;
        int c = (i & 15) * 4;
        uint4 v = *reinterpret_cast<const uint4*>(&g_Qt[base + (size_t)(q0 + r) * DMODEL + c]);
        *reinterpret_cast<uint4*>(&Qs[r * KST + c]) = v;
    }
    __syncthreads();

    // ---- Q fragments to registers: 8 k-chunks (dk=64, k8) ----
    uint32_t qa[8][4];
    #pragma unroll
    for (int kf = 0; kf < 8; kf++)
        ldsm_x4(qa[kf][0], qa[kf][1], qa[kf][2], qa[kf][3],
                sQ + (q_off + kf * 8) * 4);
    __syncthreads();

    float m_i[2] = {-CUDART_INF_F, -CUDART_INF_F};
    float l_i[2] = {0.f, 0.f};
    float o[8][4];
    #pragma unroll
    for (int nf = 0; nf < 8; nf++)
        #pragma unroll
        for (int c = 0; c < 4; c++) o[nf][c] = 0.f;

    for (int kt = 0; kt < SEQ / 64; kt++) {
        // ---- stage K (tf32 u32 copy) and V (bf16 hi/lo copy) ----
        #pragma unroll
        for (int t = 0; t < 8; t++) {
            int i = t * 128 + tid;
            int r = i >> 4;
            int c = (i & 15) * 4;
            uint4 v = *reinterpret_cast<const uint4*>(
                &g_Kt[base + (size_t)(kt * 64 + r) * DMODEL + c]);
            *reinterpret_cast<uint4*>(&Ks[r * KST + c]) = v;
        }
        #pragma unroll
        for (int t = 0; t < 4; t++) {
            int i  = t * 128 + tid;
            int r  = i >> 3;
            int c8 = (i & 7) * 8;
            size_t g = base + (size_t)(kt * 64 + r) * DMODEL + c8;
            *reinterpret_cast<uint4*>(&Vh[r * VST + c8]) =
                *reinterpret_cast<const uint4*>(&g_Vh[g]);
            *reinterpret_cast<uint4*>(&Vl[r * VST + c8]) =
                *reinterpret_cast<const uint4*>(&g_Vl[g]);
        }
        __syncthreads();

        // ---- S = Q K^T (tf32, pre-scaled) ----
        float s[8][4];
        #pragma unroll
        for (int nf = 0; nf < 8; nf++)
            #pragma unroll
            for (int c = 0; c < 4; c++) s[nf][c] = 0.f;

        #pragma unroll
        for (int kf = 0; kf < 8; kf++) {
            #pragma unroll
            for (int nfp = 0; nfp < 4; nfp++) {
                uint32_t b0, b1, b2, b3;
                ldsm_x4(b0, b1, b2, b3,
                        sK + (k_off + nfp * 16 * KST + kf * 8) * 4);
                mma8(s[2 * nfp],     qa[kf][0], qa[kf][1], qa[kf][2], qa[kf][3], b0, b1);
                mma8(s[2 * nfp + 1], qa[kf][0], qa[kf][1], qa[kf][2], qa[kf][3], b2, b3);
            }
        }

        // ---- online softmax; P packed to bf16 hi/lo in registers ----
        uint32_t ph[8][2], pl[8][2];
        #pragma unroll
        for (int hf = 0; hf < 2; hf++) {
            float mx = -CUDART_INF_F;
            #pragma unroll
            for (int nf = 0; nf < 8; nf++)
                mx = fmaxf(mx, fmaxf(s[nf][2 * hf], s[nf][2 * hf + 1]));
            mx = fmaxf(mx, __shfl_xor_sync(0xffffffffu, mx, 1));
            mx = fmaxf(mx, __shfl_xor_sync(0xffffffffu, mx, 2));

            float m_new = fmaxf(m_i[hf], mx);
            float alpha = __expf(m_i[hf] - m_new);
            float sum = 0.f;
            #pragma unroll
            for (int nf = 0; nf < 8; nf++) {
                float p0 = __expf(s[nf][2 * hf]     - m_new);
                float p1 = __expf(s[nf][2 * hf + 1] - m_new);
                sum += p0 + p1;
                __nv_bfloat16 h0, l0, h1, l1;
                bsplit(p0, h0, l0);
                bsplit(p1, h1, l1);
                ph[nf][hf] = pk(h0, h1);
                pl[nf][hf] = pk(l0, l1);
                o[nf][2 * hf]     *= alpha;
                o[nf][2 * hf + 1] *= alpha;
            }
            sum += __shfl_xor_sync(0xffffffffu, sum, 1);
            sum += __shfl_xor_sync(0xffffffffu, sum, 2);
            l_i[hf] = l_i[hf] * alpha + sum;
            m_i[hf] = m_new;
        }

        // ---- O += P V (split-bf16, 3-term; P in registers) ----
        #pragma unroll
        for (int kf = 0; kf < 4; kf++) {
            uint32_t aph[4] = { ph[2 * kf][0], ph[2 * kf][1],
                                ph[2 * kf + 1][0], ph[2 * kf + 1][1] };
            uint32_t apl[4] = { pl[2 * kf][0], pl[2 * kf][1],
                                pl[2 * kf + 1][0], pl[2 * kf + 1][1] };
            #pragma unroll
            for (int nfp = 0; nfp < 4; nfp++) {
                int off = (v_off + kf * 16 * VST + nfp * 16) * 2;
                uint32_t bh0, bh1, bh2, bh3, bl0, bl1, bl2, bl3;
                ldsm_x4t(bh0, bh1, bh2, bh3, sVh + off);
                ldsm_x4t(bl0, bl1, bl2, bl3, sVl + off);
                mma16(o[2 * nfp],     aph, bh0, bh1);
                mma16(o[2 * nfp],     apl, bh0, bh1);
                mma16(o[2 * nfp],     aph, bl0, bl1);
                mma16(o[2 * nfp + 1], aph, bh2, bh3);
                mma16(o[2 * nfp + 1], apl, bh2, bh3);
                mma16(o[2 * nfp + 1], aph, bl2, bl3);
            }
        }
        __syncthreads();   // all warps done with Ks/Vh/Vl before restage
    }

    // ---- normalize and store ----
    float inv0 = 1.f / l_i[0];
    float inv1 = 1.f / l_i[1];
    int row = q0 + w * 16 + gid;
    #pragma unroll
    for (int nf = 0; nf < 8; nf++) {
        int col = nf * 8 + 2 * tig;
        *reinterpret_cast<float2*>(&out[base + (size_t)row * DMODEL + col]) =
            make_float2(o[nf][0] * inv0, o[nf][1] * inv0);
        *reinterpret_cast<float2*>(&out[base + (size_t)(row + 8) * DMODEL + col]) =
            make_float2(o[nf][2] * inv1, o[nf][3] * inv1);
    }
}

// ---------------------------------------------------------------------------

extern "C" void kernel_launch(void* const* d_in, const int* in_sizes, int n_in,
                              void* d_out, int out_size)
{
    const float* x  = (const float*)d_in[0];
    const float* Wq = (const float*)d_in[1];
    const float* bq = (const float*)d_in[2];
    const float* Wk = (const float*)d_in[3];
    const float* bk = (const float*)d_in[4];
    const float* Wv = (const float*)d_in[5];
    const float* bv = (const float*)d_in[6];
    float* out = (float*)d_out;

    // QKV projections (split-bf16 mma)
    {
        int smem = 4 * 128 * AST * (int)sizeof(__nv_bfloat16);   // 40960 B
        cudaFuncSetAttribute(qkv_mma_kernel,
                             cudaFuncAttributeMaxDynamicSharedMemorySize, smem);
        dim3 grid(DMODEL / 128, MROWS / 128, 3);
        qkv_mma_kernel<<<grid, 256, smem>>>(x, Wq, bq, Wk, bk, Wv, bv);
    }

    // Flash attention
    {
        int smem = 2 * 64 * KST * (int)sizeof(uint32_t)               // Qs, Ks
                 + 2 * 64 * VST * (int)sizeof(__nv_bfloat16);         // Vh, Vl
        cudaFuncSetAttribute(flash_mma_kernel,
                             cudaFuncAttributeMaxDynamicSharedMemorySize, smem);
        dim3 grid(SEQ / 64, B_SZ * NHEAD);
        flash_mma_kernel<<<grid, 128, smem>>>(out);
    }
}